// round 1
// baseline (speedup 1.0000x reference)
#include <cuda_runtime.h>
#include <cuda_bf16.h>

#define NDOF 7
#define GRAV 9.81f

struct JointParams {
    float C0[9], C1[9], C2[9];  // R(s,c) = C0 + s*C1 - c*C2
    float p[3];                 // trans_fix[d+1]
    float ax[3];                // joint axis
    float mc[3];                // m * com
    float Io[9];                // inertia + m*(|c|^2 I - c c^T)
    float m;                    // mass
    float damping;
};

__device__ JointParams g_par[NDOF];

__device__ __forceinline__ void mat3mul(const float* A, const float* B, float* C) {
#pragma unroll
    for (int i = 0; i < 3; i++)
#pragma unroll
        for (int j = 0; j < 3; j++)
            C[i*3+j] = A[i*3+0]*B[0*3+j] + A[i*3+1]*B[1*3+j] + A[i*3+2]*B[2*3+j];
}

__global__ void prep_kernel(const float* __restrict__ rot_fix,
                            const float* __restrict__ trans_fix,
                            const float* __restrict__ joint_axes,
                            const float* __restrict__ mass,
                            const float* __restrict__ com,
                            const float* __restrict__ inertia,
                            const float* __restrict__ damping) {
    int d = threadIdx.x;
    if (d >= NDOF) return;
    JointParams P;
    float a0 = joint_axes[3*d+0], a1 = joint_axes[3*d+1], a2 = joint_axes[3*d+2];
    float K[9]  = {0.f, -a2, a1,   a2, 0.f, -a0,   -a1, a0, 0.f};
    float K2[9];
    mat3mul(K, K, K2);
    const float* M0 = rot_fix + (d+1)*9;
    float M1[9], M2[9];
    mat3mul(M0, K, M1);
    mat3mul(M0, K2, M2);
#pragma unroll
    for (int k = 0; k < 9; k++) {
        P.C0[k] = M0[k] + M2[k];
        P.C1[k] = M1[k];
        P.C2[k] = M2[k];
    }
#pragma unroll
    for (int i = 0; i < 3; i++) P.p[i] = trans_fix[(d+1)*3+i];
    P.ax[0] = a0; P.ax[1] = a1; P.ax[2] = a2;
    float m = mass[d+1];
    P.m = m;
    float c0 = com[(d+1)*3+0], c1 = com[(d+1)*3+1], c2 = com[(d+1)*3+2];
    P.mc[0] = m*c0; P.mc[1] = m*c1; P.mc[2] = m*c2;
    float cc = c0*c0 + c1*c1 + c2*c2;
    float cv[3] = {c0, c1, c2};
#pragma unroll
    for (int i = 0; i < 3; i++)
#pragma unroll
        for (int j = 0; j < 3; j++)
            P.Io[i*3+j] = inertia[(d+1)*9 + i*3 + j] + m * ((i == j ? cc : 0.f) - cv[i]*cv[j]);
    P.damping = damping[d];
    g_par[d] = P;
}

__device__ __forceinline__ void rtmv(const float R[9], const float v[3], float o[3]) {
    // o = R^T v
    o[0] = R[0]*v[0] + R[3]*v[1] + R[6]*v[2];
    o[1] = R[1]*v[0] + R[4]*v[1] + R[7]*v[2];
    o[2] = R[2]*v[0] + R[5]*v[1] + R[8]*v[2];
}
__device__ __forceinline__ void rmv(const float R[9], const float v[3], float o[3]) {
    // o = R v
    o[0] = R[0]*v[0] + R[1]*v[1] + R[2]*v[2];
    o[1] = R[3]*v[0] + R[4]*v[1] + R[5]*v[2];
    o[2] = R[6]*v[0] + R[7]*v[1] + R[8]*v[2];
}
__device__ __forceinline__ void cross3(const float a[3], const float b[3], float o[3]) {
    o[0] = a[1]*b[2] - a[2]*b[1];
    o[1] = a[2]*b[0] - a[0]*b[2];
    o[2] = a[0]*b[1] - a[1]*b[0];
}
__device__ __forceinline__ void buildR(const JointParams& P, float s, float c, float R[9]) {
#pragma unroll
    for (int k = 0; k < 9; k++)
        R[k] = P.C0[k] + s*P.C1[k] - c*P.C2[k];
}

__global__ void rnea_kernel(const float* __restrict__ q,
                            const float* __restrict__ qd,
                            const float* __restrict__ qdd,
                            float* __restrict__ out, int B) {
    int b = blockIdx.x * blockDim.x + threadIdx.x;
    if (b >= B) return;

    float sn[NDOF], cs[NDOF];
    float fl[NDOF][3], fa[NDOF][3];
    float qdl[NDOF];

    float vl[3] = {0.f, 0.f, 0.f};
    float va[3] = {0.f, 0.f, 0.f};
    float al[3] = {0.f, 0.f, GRAV};
    float aa[3] = {0.f, 0.f, 0.f};

#pragma unroll
    for (int d = 0; d < NDOF; d++) {
        const JointParams& P = g_par[d];
        float qv   = q[b*NDOF + d];
        float qdv  = qd[b*NDOF + d];
        float qddv = qdd[b*NDOF + d];
        qdl[d] = qdv;

        float si, ci;
        __sincosf(qv, &si, &ci);
        sn[d] = si; cs[d] = ci;

        float R[9];
        buildR(P, si, ci, R);

        float pinv[3];
        rtmv(R, P.p, pinv);
        pinv[0] = -pinv[0]; pinv[1] = -pinv[1]; pinv[2] = -pinv[2];

        float va_n[3], t[3], cx[3];
        rtmv(R, va, va_n);
        rtmv(R, vl, t);
        cross3(pinv, va_n, cx);
        // vl_i = vl_n
        vl[0] = t[0] + cx[0]; vl[1] = t[1] + cx[1]; vl[2] = t[2] + cx[2];

        float jv[3] = {qdv*P.ax[0], qdv*P.ax[1], qdv*P.ax[2]};
        // va_i = va_n + jv
        va[0] = va_n[0] + jv[0]; va[1] = va_n[1] + jv[1]; va[2] = va_n[2] + jv[2];

        float aa_n[3], al_n[3];
        rtmv(R, aa, aa_n);
        rtmv(R, al, t);
        cross3(pinv, aa_n, cx);
        al_n[0] = t[0] + cx[0]; al_n[1] = t[1] + cx[1]; al_n[2] = t[2] + cx[2];

        // aa_i = aa_n + ja + cross(va_i, jv)
        cross3(va, jv, cx);
        aa[0] = aa_n[0] + qddv*P.ax[0] + cx[0];
        aa[1] = aa_n[1] + qddv*P.ax[1] + cx[1];
        aa[2] = aa_n[2] + qddv*P.ax[2] + cx[2];

        // al_i = al_n + cross(vl_i, jv)
        cross3(vl, jv, cx);
        al[0] = al_n[0] + cx[0]; al[1] = al_n[1] + cx[1]; al[2] = al_n[2] + cx[2];

        // ---- inertial forces for this link ----
        float Ial[3], Iaa[3], Ivl[3], Iva[3];
        cross3(aa, P.mc, cx);
        Ial[0] = P.m*al[0] + cx[0]; Ial[1] = P.m*al[1] + cx[1]; Ial[2] = P.m*al[2] + cx[2];
        rmv(P.Io, aa, t);
        cross3(P.mc, al, cx);
        Iaa[0] = t[0] + cx[0]; Iaa[1] = t[1] + cx[1]; Iaa[2] = t[2] + cx[2];

        cross3(va, P.mc, cx);
        Ivl[0] = P.m*vl[0] + cx[0]; Ivl[1] = P.m*vl[1] + cx[1]; Ivl[2] = P.m*vl[2] + cx[2];
        rmv(P.Io, va, t);
        cross3(P.mc, vl, cx);
        Iva[0] = t[0] + cx[0]; Iva[1] = t[1] + cx[1]; Iva[2] = t[2] + cx[2];

        // f_l = Ia_l + cross(va, Iv_l)
        cross3(va, Ivl, cx);
        fl[d][0] = Ial[0] + cx[0]; fl[d][1] = Ial[1] + cx[1]; fl[d][2] = Ial[2] + cx[2];
        // f_a = Ia_a + cross(va, Iv_a) + cross(vl, Iv_l)
        float cx2[3];
        cross3(va, Iva, cx);
        cross3(vl, Ivl, cx2);
        fa[d][0] = Iaa[0] + cx[0] + cx2[0];
        fa[d][1] = Iaa[1] + cx[1] + cx2[1];
        fa[d][2] = Iaa[2] + cx[2] + cx2[2];
    }

    // ---- backward scan ----
    float cl[3] = {0.f, 0.f, 0.f};
    float ca[3] = {0.f, 0.f, 0.f};
#pragma unroll
    for (int d = NDOF - 1; d >= 0; d--) {
        const JointParams& P = g_par[d];
        float R[9];
        buildR(P, sn[d], cs[d], R);

        float tl[3] = {fl[d][0] + cl[0], fl[d][1] + cl[1], fl[d][2] + cl[2]};
        float ta[3] = {fa[d][0] + ca[0], fa[d][1] + ca[1], fa[d][2] + ca[2]};

        float tau = ta[0]*P.ax[0] + ta[1]*P.ax[1] + ta[2]*P.ax[2];

        float nl[3], t[3], cx[3];
        rmv(R, tl, nl);
        rmv(R, ta, t);
        cross3(P.p, nl, cx);
        cl[0] = nl[0]; cl[1] = nl[1]; cl[2] = nl[2];
        ca[0] = t[0] + cx[0]; ca[1] = t[1] + cx[1]; ca[2] = t[2] + cx[2];

        out[b*NDOF + d] = tau + P.damping * qdl[d];
    }
}

extern "C" void kernel_launch(void* const* d_in, const int* in_sizes, int n_in,
                              void* d_out, int out_size) {
    const float* q          = (const float*)d_in[0];
    const float* qd         = (const float*)d_in[1];
    const float* qdd_des    = (const float*)d_in[2];
    const float* rot_fix    = (const float*)d_in[3];
    const float* trans_fix  = (const float*)d_in[4];
    const float* joint_axes = (const float*)d_in[5];
    const float* mass       = (const float*)d_in[6];
    const float* com        = (const float*)d_in[7];
    const float* inertia    = (const float*)d_in[8];
    const float* damping    = (const float*)d_in[9];
    float* out = (float*)d_out;

    int B = in_sizes[0] / NDOF;

    prep_kernel<<<1, 32>>>(rot_fix, trans_fix, joint_axes, mass, com, inertia, damping);

    int threads = 256;
    int blocks = (B + threads - 1) / threads;
    rnea_kernel<<<blocks, threads>>>(q, qd, qdd_des, out, B);
}

// round 2
// speedup vs baseline: 1.4456x; 1.4456x over previous
#include <cuda_runtime.h>
#include <cuda_bf16.h>

#define NDOF 7
#define GRAV 9.81f
#define TPB 128

struct JointParams {
    float C0[9], C1[9], C2[9];  // R(s,c) = C0 + s*C1 - c*C2
    float u0[3], u1[3], u2[3];  // u_k = C_k^T p  (so R^T p = u0 + s*u1 - c*u2)
    float p[3];                 // trans_fix[d+1]
    float ax[3];                // joint axis
    float mc[3];                // m * com
    float Io[9];                // inertia + m*(|c|^2 I - c c^T)
    float m;
    float damping;
};

__device__ JointParams g_stage[NDOF];
__constant__ JointParams c_par[NDOF];

__device__ __forceinline__ void mat3mul(const float* A, const float* B, float* C) {
#pragma unroll
    for (int i = 0; i < 3; i++)
#pragma unroll
        for (int j = 0; j < 3; j++)
            C[i*3+j] = A[i*3+0]*B[0*3+j] + A[i*3+1]*B[1*3+j] + A[i*3+2]*B[2*3+j];
}

__global__ void prep_kernel(const float* __restrict__ rot_fix,
                            const float* __restrict__ trans_fix,
                            const float* __restrict__ joint_axes,
                            const float* __restrict__ mass,
                            const float* __restrict__ com,
                            const float* __restrict__ inertia,
                            const float* __restrict__ damping) {
    int d = threadIdx.x;
    if (d >= NDOF) return;
    JointParams P;
    float a0 = joint_axes[3*d+0], a1 = joint_axes[3*d+1], a2 = joint_axes[3*d+2];
    float K[9]  = {0.f, -a2, a1,   a2, 0.f, -a0,   -a1, a0, 0.f};
    float K2[9];
    mat3mul(K, K, K2);
    const float* M0 = rot_fix + (d+1)*9;
    float M1[9], M2[9];
    mat3mul(M0, K, M1);
    mat3mul(M0, K2, M2);
#pragma unroll
    for (int k = 0; k < 9; k++) {
        P.C0[k] = M0[k] + M2[k];
        P.C1[k] = M1[k];
        P.C2[k] = M2[k];
    }
    float p0 = trans_fix[(d+1)*3+0], p1 = trans_fix[(d+1)*3+1], p2 = trans_fix[(d+1)*3+2];
    P.p[0] = p0; P.p[1] = p1; P.p[2] = p2;
#pragma unroll
    for (int j = 0; j < 3; j++) {
        P.u0[j] = P.C0[0*3+j]*p0 + P.C0[1*3+j]*p1 + P.C0[2*3+j]*p2;
        P.u1[j] = P.C1[0*3+j]*p0 + P.C1[1*3+j]*p1 + P.C1[2*3+j]*p2;
        P.u2[j] = P.C2[0*3+j]*p0 + P.C2[1*3+j]*p1 + P.C2[2*3+j]*p2;
    }
    P.ax[0] = a0; P.ax[1] = a1; P.ax[2] = a2;
    float m = mass[d+1];
    P.m = m;
    float c0 = com[(d+1)*3+0], c1 = com[(d+1)*3+1], c2 = com[(d+1)*3+2];
    P.mc[0] = m*c0; P.mc[1] = m*c1; P.mc[2] = m*c2;
    float cc = c0*c0 + c1*c1 + c2*c2;
    float cv[3] = {c0, c1, c2};
#pragma unroll
    for (int i = 0; i < 3; i++)
#pragma unroll
        for (int j = 0; j < 3; j++)
            P.Io[i*3+j] = inertia[(d+1)*9 + i*3 + j] + m * ((i == j ? cc : 0.f) - cv[i]*cv[j]);
    P.damping = damping[d];
    g_stage[d] = P;
}

__device__ __forceinline__ void rtmv(const float R[9], const float v[3], float o[3]) {
    o[0] = R[0]*v[0] + R[3]*v[1] + R[6]*v[2];
    o[1] = R[1]*v[0] + R[4]*v[1] + R[7]*v[2];
    o[2] = R[2]*v[0] + R[5]*v[1] + R[8]*v[2];
}
__device__ __forceinline__ void rmv(const float R[9], const float v[3], float o[3]) {
    o[0] = R[0]*v[0] + R[1]*v[1] + R[2]*v[2];
    o[1] = R[3]*v[0] + R[4]*v[1] + R[5]*v[2];
    o[2] = R[6]*v[0] + R[7]*v[1] + R[8]*v[2];
}
__device__ __forceinline__ void cross3(const float a[3], const float b[3], float o[3]) {
    o[0] = a[1]*b[2] - a[2]*b[1];
    o[1] = a[2]*b[0] - a[0]*b[2];
    o[2] = a[0]*b[1] - a[1]*b[0];
}
__device__ __forceinline__ void buildR(const JointParams& P, float s, float c, float R[9]) {
#pragma unroll
    for (int k = 0; k < 9; k++)
        R[k] = P.C0[k] + s*P.C1[k] - c*P.C2[k];
}

__global__ void __launch_bounds__(TPB, 4)
rnea_kernel(const float* __restrict__ q,
            const float* __restrict__ qd,
            const float* __restrict__ qdd,
            float* __restrict__ out, int B) {
    __shared__ float sq[TPB*NDOF], sqd[TPB*NDOF], sqdd[TPB*NDOF];
    const int t = threadIdx.x;
    const long base = (long)blockIdx.x * (TPB * NDOF);
    const long total = (long)B * NDOF;

    // coalesced staging of inputs
#pragma unroll
    for (int i = 0; i < NDOF; i++) {
        int idx = i * TPB + t;
        long g = base + idx;
        float a = 0.f, bb = 0.f, c = 0.f;
        if (g < total) { a = q[g]; bb = qd[g]; c = qdd[g]; }
        sq[idx] = a; sqd[idx] = bb; sqdd[idx] = c;
    }
    __syncthreads();

    float fl[NDOF][3], fa[NDOF][3];

    float vl[3] = {0.f, 0.f, 0.f};
    float va[3] = {0.f, 0.f, 0.f};
    float al[3] = {0.f, 0.f, GRAV};
    float aa[3] = {0.f, 0.f, 0.f};

#pragma unroll
    for (int d = 0; d < NDOF; d++) {
        const JointParams& P = c_par[d];
        float qv   = sq [t*NDOF + d];
        float qdv  = sqd[t*NDOF + d];
        float qddv = sqdd[t*NDOF + d];

        float si, ci;
        __sincosf(qv, &si, &ci);

        float R[9];
        buildR(P, si, ci, R);

        float pinv[3];
#pragma unroll
        for (int j = 0; j < 3; j++)
            pinv[j] = -(P.u0[j] + si*P.u1[j] - ci*P.u2[j]);

        float va_n[3], tv[3], cx[3];
        rtmv(R, va, va_n);
        rtmv(R, vl, tv);
        cross3(pinv, va_n, cx);
        vl[0] = tv[0] + cx[0]; vl[1] = tv[1] + cx[1]; vl[2] = tv[2] + cx[2];

        float jv[3] = {qdv*P.ax[0], qdv*P.ax[1], qdv*P.ax[2]};
        va[0] = va_n[0] + jv[0]; va[1] = va_n[1] + jv[1]; va[2] = va_n[2] + jv[2];

        float aa_n[3], al_n[3];
        rtmv(R, aa, aa_n);
        rtmv(R, al, tv);
        cross3(pinv, aa_n, cx);
        al_n[0] = tv[0] + cx[0]; al_n[1] = tv[1] + cx[1]; al_n[2] = tv[2] + cx[2];

        cross3(va, jv, cx);
        aa[0] = aa_n[0] + qddv*P.ax[0] + cx[0];
        aa[1] = aa_n[1] + qddv*P.ax[1] + cx[1];
        aa[2] = aa_n[2] + qddv*P.ax[2] + cx[2];

        cross3(vl, jv, cx);
        al[0] = al_n[0] + cx[0]; al[1] = al_n[1] + cx[1]; al[2] = al_n[2] + cx[2];

        // inertial wrench for this link
        float Ial[3], Iaa[3], Ivl[3], Iva[3];
        cross3(aa, P.mc, cx);
        Ial[0] = P.m*al[0] + cx[0]; Ial[1] = P.m*al[1] + cx[1]; Ial[2] = P.m*al[2] + cx[2];
        rmv(P.Io, aa, tv);
        cross3(P.mc, al, cx);
        Iaa[0] = tv[0] + cx[0]; Iaa[1] = tv[1] + cx[1]; Iaa[2] = tv[2] + cx[2];

        cross3(va, P.mc, cx);
        Ivl[0] = P.m*vl[0] + cx[0]; Ivl[1] = P.m*vl[1] + cx[1]; Ivl[2] = P.m*vl[2] + cx[2];
        rmv(P.Io, va, tv);
        cross3(P.mc, vl, cx);
        Iva[0] = tv[0] + cx[0]; Iva[1] = tv[1] + cx[1]; Iva[2] = tv[2] + cx[2];

        cross3(va, Ivl, cx);
        fl[d][0] = Ial[0] + cx[0]; fl[d][1] = Ial[1] + cx[1]; fl[d][2] = Ial[2] + cx[2];
        float cx2[3];
        cross3(va, Iva, cx);
        cross3(vl, Ivl, cx2);
        fa[d][0] = Iaa[0] + cx[0] + cx2[0];
        fa[d][1] = Iaa[1] + cx[1] + cx2[1];
        fa[d][2] = Iaa[2] + cx[2] + cx2[2];
    }

    // backward scan (recompute R from staged q; recompute damping term from staged qd)
    float cl[3] = {0.f, 0.f, 0.f};
    float ca[3] = {0.f, 0.f, 0.f};
#pragma unroll
    for (int d = NDOF - 1; d >= 0; d--) {
        const JointParams& P = c_par[d];
        float qv  = sq [t*NDOF + d];
        float qdv = sqd[t*NDOF + d];
        float si, ci;
        __sincosf(qv, &si, &ci);
        float R[9];
        buildR(P, si, ci, R);

        float tl[3] = {fl[d][0] + cl[0], fl[d][1] + cl[1], fl[d][2] + cl[2]};
        float ta[3] = {fa[d][0] + ca[0], fa[d][1] + ca[1], fa[d][2] + ca[2]};

        float tau = ta[0]*P.ax[0] + ta[1]*P.ax[1] + ta[2]*P.ax[2] + P.damping * qdv;

        float nl[3], tv[3], cx[3];
        rmv(R, tl, nl);
        rmv(R, ta, tv);
        cross3(P.p, nl, cx);
        cl[0] = nl[0]; cl[1] = nl[1]; cl[2] = nl[2];
        ca[0] = tv[0] + cx[0]; ca[1] = tv[1] + cx[1]; ca[2] = tv[2] + cx[2];

        sqdd[t*NDOF + d] = tau;   // reuse qdd staging as output buffer (own slots only)
    }

    __syncthreads();
    // coalesced output store
#pragma unroll
    for (int i = 0; i < NDOF; i++) {
        int idx = i * TPB + t;
        long g = base + idx;
        if (g < total) out[g] = sqdd[idx];
    }
}

extern "C" void kernel_launch(void* const* d_in, const int* in_sizes, int n_in,
                              void* d_out, int out_size) {
    const float* q          = (const float*)d_in[0];
    const float* qd         = (const float*)d_in[1];
    const float* qdd_des    = (const float*)d_in[2];
    const float* rot_fix    = (const float*)d_in[3];
    const float* trans_fix  = (const float*)d_in[4];
    const float* joint_axes = (const float*)d_in[5];
    const float* mass       = (const float*)d_in[6];
    const float* com        = (const float*)d_in[7];
    const float* inertia    = (const float*)d_in[8];
    const float* damping    = (const float*)d_in[9];
    float* out = (float*)d_out;

    int B = in_sizes[0] / NDOF;

    prep_kernel<<<1, 32>>>(rot_fix, trans_fix, joint_axes, mass, com, inertia, damping);

    void* src = nullptr;
    cudaGetSymbolAddress(&src, g_stage);
    cudaMemcpyToSymbolAsync(c_par, src, sizeof(JointParams) * NDOF, 0,
                            cudaMemcpyDeviceToDevice, 0);

    int blocks = (B + TPB - 1) / TPB;
    rnea_kernel<<<blocks, TPB>>>(q, qd, qdd_des, out, B);
}